// round 5
// baseline (speedup 1.0000x reference)
#include <cuda_runtime.h>
#include <cuda_bf16.h>
#include <cstdint>
#include <math.h>

#define NBATCH 2
#define SEQ    4096
#define EMB    1024
#define FFDIM  4096
#define MROWS  (NBATCH*SEQ)   // 8192

// ---------------- scratch (device globals; allocation-free) ----------------
__device__ float g_q [MROWS * EMB];
__device__ float g_k [MROWS * EMB];
__device__ float g_vt[NBATCH * EMB * SEQ];   // V transposed per batch [E][S]
__device__ float g_x [MROWS * EMB];
__device__ float g_h [MROWS * FFDIM];        // FFN hidden / attn fallback
__device__ float g_y [MROWS * EMB];

// ---------------- helpers ----------------
__device__ __forceinline__ uint32_t smem_u32(const void* p) {
    uint32_t a;
    asm("{ .reg .u64 t; cvta.to.shared.u64 t, %1; cvt.u32.u64 %0, t; }" : "=r"(a) : "l"(p));
    return a;
}
#define SW128(o) (((uint32_t)(o)) ^ ((((uint32_t)(o)) >> 3) & 0x70u))

__device__ __forceinline__ void ldsm4(uint32_t r[4], uint32_t addr) {
    asm volatile("ldmatrix.sync.aligned.m8n8.x4.shared.b16 {%0,%1,%2,%3}, [%4];"
                 : "=r"(r[0]), "=r"(r[1]), "=r"(r[2]), "=r"(r[3]) : "r"(addr));
}
__device__ __forceinline__ void mma16816(float c[4], const uint32_t a[4],
                                         uint32_t b0, uint32_t b1) {
    asm volatile("mma.sync.aligned.m16n8k16.row.col.f32.bf16.bf16.f32 "
                 "{%0,%1,%2,%3}, {%4,%5,%6,%7}, {%8,%9}, {%0,%1,%2,%3};"
                 : "+f"(c[0]), "+f"(c[1]), "+f"(c[2]), "+f"(c[3])
                 : "r"(a[0]), "r"(a[1]), "r"(a[2]), "r"(a[3]), "r"(b0), "r"(b1));
}

// fp32x8 -> bf16 hi/lo, two 16B stores into swizzled SMEM
__device__ __forceinline__ void cvt8_store(uint32_t a_hi, uint32_t a_lo,
                                           const float4& f0, const float4& f1) {
    float xs[8] = {f0.x, f0.y, f0.z, f0.w, f1.x, f1.y, f1.z, f1.w};
    uint32_t H[4], L[4];
    #pragma unroll
    for (int i = 0; i < 4; i++) {
        float a = xs[2*i], b = xs[2*i+1];
        __nv_bfloat162 hp = __floats2bfloat162_rn(a, b);   // .x = a (low half)
        float ha = __bfloat162float(hp.x), hb = __bfloat162float(hp.y);
        __nv_bfloat162 lp = __floats2bfloat162_rn(a - ha, b - hb);
        H[i] = *reinterpret_cast<uint32_t*>(&hp);
        L[i] = *reinterpret_cast<uint32_t*>(&lp);
    }
    asm volatile("st.shared.v4.b32 [%0], {%1,%2,%3,%4};"
                 :: "r"(a_hi), "r"(H[0]), "r"(H[1]), "r"(H[2]), "r"(H[3]) : "memory");
    asm volatile("st.shared.v4.b32 [%0], {%1,%2,%3,%4};"
                 :: "r"(a_lo), "r"(L[0]), "r"(L[1]), "r"(L[2]), "r"(L[3]) : "memory");
}

struct F8 { float4 a, b; };
__device__ __forceinline__ F8 ldg8(const float* p) {
    F8 r; r.a = *(const float4*)p; r.b = *(const float4*)(p + 4); return r;
}

// ---------------- HMMA GEMM: C[M,N] = op( A[M,K] @ B[N,K]^T ) ----------------
// SMEM stage layout: per stage 32KB: A[128 rows][128B = hi(64B)|lo(64B)], then B same.
// EPI: 0 = +bias, 1 = relu(+bias), 2 = sigmoid(acc*scale), 3 = +bias, write V^T
#define STAGE_BYTES 32768
#define EPI_PITCH   132
#define SMEM_TOTAL  (1024 + 2*STAGE_BYTES + 2048)   // also covers epi (128*132*4 = 67584)

template<int EPI>
__global__ void __launch_bounds__(256)
hmma_gemm(const float* __restrict__ A, const float* __restrict__ A2,
          const float* __restrict__ B, const float* __restrict__ bias,
          float* __restrict__ C, int K, int ldC,
          size_t sAs, size_t sBs, size_t sCs, float scale)
{
    extern __shared__ char smem[];
    const uint32_t sb0 = smem_u32(smem);
    const uint32_t sbA = (sb0 + 1023) & ~1023u;   // 1KB-aligned stage base

    const int t = threadIdx.x;
    const int w = t >> 5, lane = t & 31;
    const int wm = w >> 2, wn = w & 3;            // warp grid 2 x 4

    const int bz = blockIdx.z;
    A += (size_t)bz * sAs;
    if (A2) A2 += (size_t)bz * sAs;
    B += (size_t)bz * sBs;
    C += (size_t)bz * sCs;
    const int mBase = blockIdx.y * 128;
    const int nBase = blockIdx.x * 128;

    // staging indices: 2 segments per thread per matrix; each = 8 floats of one row
    int am[2], ak[2];
    #pragma unroll
    for (int i = 0; i < 2; i++) {
        const int idx = t + i * 256;
        am[i] = idx >> 2;
        ak[i] = (idx & 3) << 3;
    }

    float acc[4][4][4];
    #pragma unroll
    for (int mi = 0; mi < 4; mi++)
        #pragma unroll
        for (int nj = 0; nj < 4; nj++)
            #pragma unroll
            for (int e = 0; e < 4; e++)
                acc[mi][nj][e] = 0.f;

    const int nk = K >> 5;

    // ldmatrix address components (stage-base invariant)
    // A: row = wm*64 + mi*16 + (lane&15); kbyte = hilo*64 + ki*32 + (lane>>4)*16
    uint32_t aoff[2][2][4];  // [hilo][ki][mi]
    #pragma unroll
    for (int hl = 0; hl < 2; hl++)
        #pragma unroll
        for (int ki = 0; ki < 2; ki++)
            #pragma unroll
            for (int mi = 0; mi < 4; mi++) {
                const uint32_t row = wm * 64 + mi * 16 + (lane & 15);
                const uint32_t col = hl * 64 + ki * 32 + ((lane >> 4) << 4);
                aoff[hl][ki][mi] = SW128(row * 128 + col);
            }
    // B: row = wn*32 + nx*16 + ((lane>>4)<<3) + (lane&7); kbyte = hilo*64 + ki*32 + ((lane>>3)&1)*16
    uint32_t boff[2][2][2];  // [hilo][ki][nx]
    #pragma unroll
    for (int hl = 0; hl < 2; hl++)
        #pragma unroll
        for (int ki = 0; ki < 2; ki++)
            #pragma unroll
            for (int nx = 0; nx < 2; nx++) {
                const uint32_t row = wn * 32 + nx * 16 + ((lane >> 4) << 3) + (lane & 7);
                const uint32_t col = hl * 64 + ki * 32 + (((lane >> 3) & 1) << 4);
                boff[hl][ki][nx] = SW128(row * 128 + col);
            }

    F8 ra[2], rb[2];
    auto LOAD = [&](int kc) {
        const int kb = kc << 5;
        #pragma unroll
        for (int i = 0; i < 2; i++) {
            const float* ga = A + (size_t)(mBase + am[i]) * K + kb + ak[i];
            ra[i] = ldg8(ga);
            if (A2) {
                const F8 e = ldg8(A2 + (size_t)(mBase + am[i]) * K + kb + ak[i]);
                ra[i].a.x += e.a.x; ra[i].a.y += e.a.y; ra[i].a.z += e.a.z; ra[i].a.w += e.a.w;
                ra[i].b.x += e.b.x; ra[i].b.y += e.b.y; ra[i].b.z += e.b.z; ra[i].b.w += e.b.w;
            }
            rb[i] = ldg8(B + (size_t)(nBase + am[i]) * K + kb + ak[i]);
        }
    };
    auto STORE = [&](int s) {
        const uint32_t sA = sbA + (uint32_t)s * STAGE_BYTES;
        const uint32_t sB = sA + 16384;
        #pragma unroll
        for (int i = 0; i < 2; i++) {
            const uint32_t base = (uint32_t)(am[i] * 128 + ak[i] * 2);
            cvt8_store(sA + SW128(base), sA + SW128(base + 64), ra[i].a, ra[i].b);
            cvt8_store(sB + SW128(base), sB + SW128(base + 64), rb[i].a, rb[i].b);
        }
    };
    auto COMPUTE = [&](int s) {
        const uint32_t sA = sbA + (uint32_t)s * STAGE_BYTES;
        const uint32_t sB = sA + 16384;
        #pragma unroll
        for (int ki = 0; ki < 2; ki++) {
            uint32_t Ah[4][4], Al[4][4], Bh[4][2], Bl[4][2];
            #pragma unroll
            for (int mi = 0; mi < 4; mi++) {
                ldsm4(Ah[mi], sA + aoff[0][ki][mi]);
                ldsm4(Al[mi], sA + aoff[1][ki][mi]);
            }
            #pragma unroll
            for (int nx = 0; nx < 2; nx++) {
                uint32_t th[4], tl[4];
                ldsm4(th, sB + boff[0][ki][nx]);
                ldsm4(tl, sB + boff[1][ki][nx]);
                Bh[nx*2][0] = th[0]; Bh[nx*2][1] = th[1];
                Bh[nx*2+1][0] = th[2]; Bh[nx*2+1][1] = th[3];
                Bl[nx*2][0] = tl[0]; Bl[nx*2][1] = tl[1];
                Bl[nx*2+1][0] = tl[2]; Bl[nx*2+1][1] = tl[3];
            }
            #pragma unroll
            for (int mi = 0; mi < 4; mi++)
                #pragma unroll
                for (int nj = 0; nj < 4; nj++) {
                    mma16816(acc[mi][nj], Ah[mi], Bh[nj][0], Bh[nj][1]);
                    mma16816(acc[mi][nj], Ah[mi], Bl[nj][0], Bl[nj][1]);
                    mma16816(acc[mi][nj], Al[mi], Bh[nj][0], Bh[nj][1]);
                }
        }
    };

    // prologue: fill stage 0
    LOAD(0);
    STORE(0);
    __syncthreads();

    for (int kc = 0; kc < nk; kc++) {
        const int s = kc & 1;
        const bool more = (kc + 1 < nk);
        if (more) LOAD(kc + 1);       // LDG in flight under compute
        COMPUTE(s);
        __syncthreads();              // everyone done reading buf s^1 (prev) & this
        if (more) {
            STORE(s ^ 1);
            __syncthreads();
        }
    }

    // ---- epilogue: regs -> SMEM (pitch 132 floats) -> coalesced float4 stores
    float* epi = (float*)smem;
    const int g  = lane >> 2;
    const int tq = lane & 3;
    #pragma unroll
    for (int mi = 0; mi < 4; mi++) {
        #pragma unroll
        for (int nj = 0; nj < 4; nj++) {
            const int col = wn * 32 + nj * 8 + tq * 2;
            #pragma unroll
            for (int half = 0; half < 2; half++) {
                const int m = wm * 64 + mi * 16 + g + half * 8;
                float v0 = acc[mi][nj][half*2 + 0];
                float v1 = acc[mi][nj][half*2 + 1];
                if (EPI == 2) {
                    v0 = 1.f / (1.f + __expf(-v0 * scale));
                    v1 = 1.f / (1.f + __expf(-v1 * scale));
                } else {
                    if (bias) { v0 += bias[nBase + col]; v1 += bias[nBase + col + 1]; }
                    if (EPI == 1) { v0 = fmaxf(v0, 0.f); v1 = fmaxf(v1, 0.f); }
                }
                if (EPI == 3) {
                    epi[(col)     * EPI_PITCH + m] = v0;
                    epi[(col + 1) * EPI_PITCH + m] = v1;
                } else {
                    epi[m * EPI_PITCH + col]     = v0;
                    epi[m * EPI_PITCH + col + 1] = v1;
                }
            }
        }
    }
    __syncthreads();

    const int r  = t >> 1;
    const int ch = (t & 1) * 64;
    if (EPI == 3) {
        // epi holds tile as [n][m]; write V^T[batch][nGlob][mGlob]
        const size_t boffs = (size_t)(mBase >> 12) * ((size_t)EMB * SEQ);
        float* Cp = C + boffs + (size_t)(nBase + r) * SEQ + (mBase & (SEQ - 1)) + ch;
        #pragma unroll
        for (int i = 0; i < 16; i++) {
            const float* e = &epi[r * EPI_PITCH + ch + i * 4];
            *(float4*)(Cp + i * 4) = make_float4(e[0], e[1], e[2], e[3]);
        }
    } else {
        float* Cp = C + (size_t)(mBase + r) * ldC + nBase + ch;
        #pragma unroll
        for (int i = 0; i < 16; i++) {
            const float* e = &epi[r * EPI_PITCH + ch + i * 4];
            *(float4*)(Cp + i * 4) = make_float4(e[0], e[1], e[2], e[3]);
        }
    }
}

// ---------------- LayerNorm ----------------
__global__ void __launch_bounds__(256)
layernorm_kernel(const float* __restrict__ x, const float* __restrict__ g,
                 const float* __restrict__ b, float* __restrict__ out)
{
    const int row = blockIdx.x;
    const float* xr = x + (size_t)row * EMB;
    float* orow = out + (size_t)row * EMB;
    const int t = threadIdx.x;

    const float4 v = *(const float4*)(xr + t * 4);
    float s  = v.x + v.y + v.z + v.w;
    float ss = v.x * v.x + v.y * v.y + v.z * v.z + v.w * v.w;

    __shared__ float shs[8], shss[8], shmu[1], shinv[1];
    const int lane = t & 31, w = t >> 5;
    #pragma unroll
    for (int o = 16; o > 0; o >>= 1) {
        s  += __shfl_down_sync(0xffffffffu, s,  o);
        ss += __shfl_down_sync(0xffffffffu, ss, o);
    }
    if (lane == 0) { shs[w] = s; shss[w] = ss; }
    __syncthreads();
    if (w == 0) {
        float s2  = (lane < 8) ? shs[lane]  : 0.f;
        float ss2 = (lane < 8) ? shss[lane] : 0.f;
        #pragma unroll
        for (int o = 4; o > 0; o >>= 1) {
            s2  += __shfl_down_sync(0xffffffffu, s2,  o);
            ss2 += __shfl_down_sync(0xffffffffu, ss2, o);
        }
        if (lane == 0) {
            const float mu  = s2 * (1.f / EMB);
            const float var = ss2 * (1.f / EMB) - mu * mu;
            shmu[0]  = mu;
            shinv[0] = rsqrtf(var + 1e-5f);
        }
    }
    __syncthreads();
    const float mu = shmu[0], inv = shinv[0];

    const float4 gv = *(const float4*)(g + t * 4);
    const float4 bv = *(const float4*)(b + t * 4);
    float4 o;
    o.x = (v.x - mu) * inv * gv.x + bv.x;
    o.y = (v.y - mu) * inv * gv.y + bv.y;
    o.z = (v.z - mu) * inv * gv.z + bv.z;
    o.w = (v.w - mu) * inv * gv.w + bv.w;
    *(float4*)(orow + t * 4) = o;
}

// ---------------- launch ----------------
extern "C" void kernel_launch(void* const* d_in, const int* in_sizes, int n_in,
                              void* d_out, int out_size)
{
    const float* value  = (const float*)d_in[0];
    const float* key_t  = (const float*)d_in[1];
    const float* query  = (const float*)d_in[2];
    const float* embed0 = (const float*)d_in[3];
    const float* Wq = (const float*)d_in[4];
    const float* bq = (const float*)d_in[5];
    const float* Wk = (const float*)d_in[6];
    const float* bk = (const float*)d_in[7];
    const float* Wv = (const float*)d_in[8];
    const float* bv = (const float*)d_in[9];
    const float* W1 = (const float*)d_in[10];
    const float* b1 = (const float*)d_in[11];
    const float* W2 = (const float*)d_in[12];
    const float* b2 = (const float*)d_in[13];
    const float* g1  = (const float*)d_in[14];
    const float* be1 = (const float*)d_in[15];
    const float* g2  = (const float*)d_in[16];
    const float* be2 = (const float*)d_in[17];

    float *q, *k, *vt, *x, *h, *y;
    cudaGetSymbolAddress((void**)&q,  g_q);
    cudaGetSymbolAddress((void**)&k,  g_k);
    cudaGetSymbolAddress((void**)&vt, g_vt);
    cudaGetSymbolAddress((void**)&x,  g_x);
    cudaGetSymbolAddress((void**)&h,  g_h);
    cudaGetSymbolAddress((void**)&y,  g_y);

    cudaFuncSetAttribute(hmma_gemm<0>, cudaFuncAttributeMaxDynamicSharedMemorySize, SMEM_TOTAL);
    cudaFuncSetAttribute(hmma_gemm<1>, cudaFuncAttributeMaxDynamicSharedMemorySize, SMEM_TOTAL);
    cudaFuncSetAttribute(hmma_gemm<2>, cudaFuncAttributeMaxDynamicSharedMemorySize, SMEM_TOTAL);
    cudaFuncSetAttribute(hmma_gemm<3>, cudaFuncAttributeMaxDynamicSharedMemorySize, SMEM_TOTAL);

    float* outp = (float*)d_out;
    const long long outElems  = (long long)MROWS * EMB;
    const long long attnElems = (long long)NBATCH * SEQ * SEQ;
    float* attn = ((long long)out_size >= outElems + attnElems) ? (outp + outElems) : h;

    dim3 blk(256);
    const float scale = 1.0f / 32.0f;

    // 1) QKV projections (embed add fused); V writes transposed
    dim3 gQKV(EMB / 128, MROWS / 128, 1);
    hmma_gemm<0><<<gQKV, blk, SMEM_TOTAL>>>(query, embed0, Wq, bq, q,  EMB, EMB, 0, 0, 0, 0.f);
    hmma_gemm<0><<<gQKV, blk, SMEM_TOTAL>>>(key_t, embed0, Wk, bk, k,  EMB, EMB, 0, 0, 0, 0.f);
    hmma_gemm<3><<<gQKV, blk, SMEM_TOTAL>>>(value, embed0, Wv, bv, vt, EMB, EMB, 0, 0, 0, 0.f);

    // 2) attn = sigmoid(q @ k^T * scale), per batch
    dim3 gS(SEQ / 128, SEQ / 128, NBATCH);
    hmma_gemm<2><<<gS, blk, SMEM_TOTAL>>>(q, nullptr, k, nullptr, attn, EMB, SEQ,
                                          (size_t)SEQ * EMB, (size_t)SEQ * EMB, (size_t)SEQ * SEQ, scale);

    // 3) x = attn @ v  (= attn @ (V^T)^T), per batch
    dim3 gAV(EMB / 128, SEQ / 128, NBATCH);
    hmma_gemm<0><<<gAV, blk, SMEM_TOTAL>>>(attn, nullptr, vt, nullptr, x, SEQ, EMB,
                                           (size_t)SEQ * SEQ, (size_t)EMB * SEQ, (size_t)SEQ * EMB, 0.f);

    // 4) LN1 in place
    layernorm_kernel<<<MROWS, 256>>>(x, g1, be1, x);

    // 5) FFN1 = relu(x @ W1^T + b1)
    dim3 gF1(FFDIM / 128, MROWS / 128, 1);
    hmma_gemm<1><<<gF1, blk, SMEM_TOTAL>>>(x, nullptr, W1, b1, h, EMB, FFDIM, 0, 0, 0, 0.f);

    // 6) FFN2 = h @ W2^T + b2
    dim3 gF2(EMB / 128, MROWS / 128, 1);
    hmma_gemm<0><<<gF2, blk, SMEM_TOTAL>>>(h, nullptr, W2, b2, y, FFDIM, EMB, 0, 0, 0, 0.f);

    // 7) LN2 -> out
    layernorm_kernel<<<MROWS, 256>>>(y, g2, be2, outp);
}

// round 6
// speedup vs baseline: 1.0952x; 1.0952x over previous
#include <cuda_runtime.h>
#include <cuda_bf16.h>
#include <cstdint>
#include <math.h>

#define NBATCH 2
#define SEQ    4096
#define EMB    1024
#define FFDIM  4096
#define MROWS  (NBATCH*SEQ)   // 8192

typedef __nv_bfloat16 bf16;

// ---------------- scratch (device globals; allocation-free) ----------------
// pre-split bf16 planes
__device__ bf16 qin_hi[MROWS*EMB], qin_lo[MROWS*EMB];
__device__ bf16 kin_hi[MROWS*EMB], kin_lo[MROWS*EMB];
__device__ bf16 vin_hi[MROWS*EMB], vin_lo[MROWS*EMB];
__device__ bf16 wq_hi[EMB*EMB],   wq_lo[EMB*EMB];
__device__ bf16 wk_hi[EMB*EMB],   wk_lo[EMB*EMB];
__device__ bf16 wv_hi[EMB*EMB],   wv_lo[EMB*EMB];
__device__ bf16 w1_hi[FFDIM*EMB], w1_lo[FFDIM*EMB];
__device__ bf16 w2_hi[EMB*FFDIM], w2_lo[EMB*FFDIM];
__device__ bf16 q_hi[MROWS*EMB],  q_lo[MROWS*EMB];
__device__ bf16 k_hi[MROWS*EMB],  k_lo[MROWS*EMB];
__device__ bf16 vt_hi[NBATCH*EMB*SEQ], vt_lo[NBATCH*EMB*SEQ];
__device__ bf16 at_hi[(size_t)NBATCH*SEQ*SEQ], at_lo[(size_t)NBATCH*SEQ*SEQ];
__device__ bf16 x_hi[MROWS*EMB],  x_lo[MROWS*EMB];
__device__ bf16 h_hi[MROWS*FFDIM], h_lo[MROWS*FFDIM];
// fp32 intermediates
__device__ float g_attnf[(size_t)NBATCH*SEQ*SEQ];   // fallback if out buffer lacks attn space
__device__ float g_x[MROWS*EMB];
__device__ float g_y[MROWS*EMB];

// ---------------- helpers ----------------
__device__ __forceinline__ uint32_t smem_u32(const void* p) {
    uint32_t a;
    asm("{ .reg .u64 t; cvta.to.shared.u64 t, %1; cvt.u32.u64 %0, t; }" : "=r"(a) : "l"(p));
    return a;
}
__device__ __forceinline__ void ldsm4(uint32_t r[4], uint32_t addr) {
    asm volatile("ldmatrix.sync.aligned.m8n8.x4.shared.b16 {%0,%1,%2,%3}, [%4];"
                 : "=r"(r[0]), "=r"(r[1]), "=r"(r[2]), "=r"(r[3]) : "r"(addr));
}
__device__ __forceinline__ void mma16816(float c[4], const uint32_t a[4],
                                         uint32_t b0, uint32_t b1) {
    asm volatile("mma.sync.aligned.m16n8k16.row.col.f32.bf16.bf16.f32 "
                 "{%0,%1,%2,%3}, {%4,%5,%6,%7}, {%8,%9}, {%0,%1,%2,%3};"
                 : "+f"(c[0]), "+f"(c[1]), "+f"(c[2]), "+f"(c[3])
                 : "r"(a[0]), "r"(a[1]), "r"(a[2]), "r"(a[3]), "r"(b0), "r"(b1));
}
__device__ __forceinline__ void cpasync16(uint32_t dst, const void* src) {
    asm volatile("cp.async.cg.shared.global [%0], [%1], 16;" :: "r"(dst), "l"(src) : "memory");
}
#define CP_COMMIT() asm volatile("cp.async.commit_group;" ::: "memory")
#define CP_WAIT(n)  asm volatile("cp.async.wait_group %0;" :: "n"(n) : "memory")

// fp32x4 -> hi/lo bf16x4 (as uint2 each)
__device__ __forceinline__ void split4(const float4& f, uint2& H, uint2& L) {
    __nv_bfloat162 h0 = __floats2bfloat162_rn(f.x, f.y);
    __nv_bfloat162 h1 = __floats2bfloat162_rn(f.z, f.w);
    __nv_bfloat162 l0 = __floats2bfloat162_rn(f.x - __bfloat162float(h0.x),
                                              f.y - __bfloat162float(h0.y));
    __nv_bfloat162 l1 = __floats2bfloat162_rn(f.z - __bfloat162float(h1.x),
                                              f.w - __bfloat162float(h1.y));
    H.x = *reinterpret_cast<uint32_t*>(&h0);
    H.y = *reinterpret_cast<uint32_t*>(&h1);
    L.x = *reinterpret_cast<uint32_t*>(&l0);
    L.y = *reinterpret_cast<uint32_t*>(&l1);
}

// ---------------- elementwise converters ----------------
// hi/lo split of (a [+ b]); n elements, 4 per thread
__global__ void __launch_bounds__(256)
cvt_split(const float* __restrict__ a, const float* __restrict__ b,
          bf16* __restrict__ hi, bf16* __restrict__ lo)
{
    const size_t i4 = ((size_t)blockIdx.x * 256 + threadIdx.x) * 4;
    float4 f = *(const float4*)(a + i4);
    if (b) {
        const float4 e = *(const float4*)(b + i4);
        f.x += e.x; f.y += e.y; f.z += e.z; f.w += e.w;
    }
    uint2 H, L;
    split4(f, H, L);
    *(uint2*)(hi + i4) = H;
    *(uint2*)(lo + i4) = L;
}

// ---------------- HMMA GEMM: C[M,N] = op( A[M,K] @ B[N,K]^T ) ----------------
// Inputs are pre-split bf16 hi/lo planes. 3-stage cp.async pipeline.
// SMEM stage (32KB): A rows 128 x [hi 64B | lo 64B] SW128, then B same.
// OP: 0 = +bias, 1 = relu(+bias), 2 = sigmoid(acc*scale)
#define NS 3
#define STAGE_BYTES 32768
#define EPI_PITCH   132
#define SMEM_TOTAL  (NS*STAGE_BYTES + 1024)

template<int OP, bool OUTF, bool OUTB, bool TRANS>
__global__ void __launch_bounds__(256, 2)
hmma_gemm(const bf16* __restrict__ Ahi, const bf16* __restrict__ Alo,
          const bf16* __restrict__ Bhi, const bf16* __restrict__ Blo,
          const float* __restrict__ bias,
          float* __restrict__ Cf, bf16* __restrict__ Chi, bf16* __restrict__ Clo,
          int K, int ldC, size_t sA, size_t sB, size_t sC, float scale)
{
    extern __shared__ char smem[];
    const uint32_t sbA0 = (smem_u32(smem) + 1023) & ~1023u;

    const int t = threadIdx.x;
    const int w = t >> 5, lane = t & 31;
    const int wm = w >> 2, wn = w & 3;            // warp grid 2 x 4

    const int bz = blockIdx.z;
    Ahi += (size_t)bz * sA;  Alo += (size_t)bz * sA;
    Bhi += (size_t)bz * sB;  Blo += (size_t)bz * sB;
    const int mBase = blockIdx.y * 128;
    const int nBase = blockIdx.x * 128;

    float acc[4][4][4];
    #pragma unroll
    for (int mi = 0; mi < 4; mi++)
        #pragma unroll
        for (int nj = 0; nj < 4; nj++)
            #pragma unroll
            for (int e = 0; e < 4; e++)
                acc[mi][nj][e] = 0.f;

    const int nk = K >> 5;

    // cp.async staging: row = t>>1 (0..127), chunk pair = t&1
    const int srow = t >> 1;
    const int scp  = (t & 1) * 2;
    const uint32_t srx = ((uint32_t)(srow & 7)) << 4;   // swizzle xor for this row
    const uint32_t sAoff = (uint32_t)srow * 128;

    auto ISSUE = [&](int kc, int s) {
        const int kb = kc << 5;
        const uint32_t stA = sbA0 + (uint32_t)s * STAGE_BYTES;
        const uint32_t stB = stA + 16384;
        #pragma unroll
        for (int c = 0; c < 2; c++) {
            const int col8 = scp + c;                   // 0..3 (8 bf16 per chunk)
            const uint32_t dh = (uint32_t)(col8 * 16);
            const size_t gA = (size_t)(mBase + srow) * K + kb + col8 * 8;
            const size_t gB = (size_t)(nBase + srow) * K + kb + col8 * 8;
            cpasync16(stA + sAoff + ((dh)      ^ srx), Ahi + gA);
            cpasync16(stA + sAoff + ((dh + 64) ^ srx), Alo + gA);
            cpasync16(stB + sAoff + ((dh)      ^ srx), Bhi + gB);
            cpasync16(stB + sAoff + ((dh + 64) ^ srx), Blo + gB);
        }
    };

    // ldmatrix address components
    const uint32_t arow128 = (uint32_t)(wm * 64 + (lane & 15)) * 128;
    const uint32_t a16     = ((uint32_t)(lane >> 4)) << 4;
    const uint32_t axor    = ((uint32_t)(lane & 7)) << 4;
    const uint32_t brow128 = (uint32_t)(wn * 32 + ((lane >> 4) << 3) + (lane & 7)) * 128;
    const uint32_t b16     = ((uint32_t)((lane >> 3) & 1)) << 4;
    const uint32_t bxor    = axor;

    auto COMPUTE = [&](int s) {
        const uint32_t stA = sbA0 + (uint32_t)s * STAGE_BYTES;
        const uint32_t stB = stA + 16384;
        #pragma unroll
        for (int ki = 0; ki < 2; ki++) {
            uint32_t Ah[4][4], Al[4][4];
            #pragma unroll
            for (int mi = 0; mi < 4; mi++) {
                ldsm4(Ah[mi], stA + arow128 + mi * 2048 + (((uint32_t)(ki*32)      + a16) ^ axor));
                ldsm4(Al[mi], stA + arow128 + mi * 2048 + (((uint32_t)(64 + ki*32) + a16) ^ axor));
            }
            #pragma unroll
            for (int nx = 0; nx < 2; nx++) {
                uint32_t th[4], tl[4];
                ldsm4(th, stB + brow128 + nx * 2048 + (((uint32_t)(ki*32)      + b16) ^ bxor));
                ldsm4(tl, stB + brow128 + nx * 2048 + (((uint32_t)(64 + ki*32) + b16) ^ bxor));
                #pragma unroll
                for (int half = 0; half < 2; half++) {
                    const int nj = nx * 2 + half;
                    #pragma unroll
                    for (int mi = 0; mi < 4; mi++) {
                        mma16816(acc[mi][nj], Ah[mi], th[half*2], th[half*2+1]);
                        mma16816(acc[mi][nj], Ah[mi], tl[half*2], tl[half*2+1]);
                        mma16816(acc[mi][nj], Al[mi], th[half*2], th[half*2+1]);
                    }
                }
            }
        }
    };

    // prologue: fill NS-1 stages
    #pragma unroll
    for (int s = 0; s < NS - 1; s++) {
        ISSUE(s, s);
        CP_COMMIT();
    }

    for (int kc = 0; kc < nk; kc++) {
        CP_WAIT(NS - 2);
        __syncthreads();
        const int s = kc % NS;
        const int kn = kc + NS - 1;
        if (kn < nk) {
            ISSUE(kn, kn % NS);
            CP_COMMIT();
        }
        COMPUTE(s);
    }
    __syncthreads();   // stage smem about to be reused as epilogue buffer

    // ---- epilogue: regs -> SMEM (pitch 132 floats) -> vectorized stores
    float* epi = (float*)smem;
    const int g  = lane >> 2;
    const int tq = lane & 3;
    #pragma unroll
    for (int mi = 0; mi < 4; mi++) {
        #pragma unroll
        for (int nj = 0; nj < 4; nj++) {
            const int col = wn * 32 + nj * 8 + tq * 2;
            #pragma unroll
            for (int half = 0; half < 2; half++) {
                const int m = wm * 64 + mi * 16 + g + half * 8;
                float v0 = acc[mi][nj][half*2 + 0];
                float v1 = acc[mi][nj][half*2 + 1];
                if (OP == 2) {
                    v0 = 1.f / (1.f + __expf(-v0 * scale));
                    v1 = 1.f / (1.f + __expf(-v1 * scale));
                } else {
                    if (bias) { v0 += bias[nBase + col]; v1 += bias[nBase + col + 1]; }
                    if (OP == 1) { v0 = fmaxf(v0, 0.f); v1 = fmaxf(v1, 0.f); }
                }
                if (TRANS) {
                    epi[(col)     * EPI_PITCH + m] = v0;
                    epi[(col + 1) * EPI_PITCH + m] = v1;
                } else {
                    epi[m * EPI_PITCH + col]     = v0;
                    epi[m * EPI_PITCH + col + 1] = v1;
                }
            }
        }
    }
    __syncthreads();

    const int r  = t >> 1;
    const int ch = (t & 1) * 64;
    size_t rowOff;
    if (TRANS) {
        // tile stored [n][m]; write to C^T[batch][nGlob][mGlob], ld = SEQ
        const size_t boffs = (size_t)(mBase >> 12) * ((size_t)EMB * SEQ);
        rowOff = boffs + (size_t)(nBase + r) * SEQ + (size_t)(mBase & (SEQ - 1)) + ch;
    } else {
        rowOff = (size_t)bz * sC + (size_t)(mBase + r) * ldC + nBase + ch;
    }
    #pragma unroll
    for (int i = 0; i < 16; i++) {
        const float* e = &epi[r * EPI_PITCH + ch + i * 4];
        const float4 f = make_float4(e[0], e[1], e[2], e[3]);
        if (OUTF) *(float4*)(Cf + rowOff + i * 4) = f;
        if (OUTB) {
            uint2 H, L;
            split4(f, H, L);
            *(uint2*)(Chi + rowOff + i * 4) = H;
            *(uint2*)(Clo + rowOff + i * 4) = L;
        }
    }
}

// ---------------- LayerNorm ----------------
// BF=0: write fp32; BF=1: write bf16 hi/lo split
template<int BF>
__global__ void __launch_bounds__(256)
layernorm_kernel(const float* __restrict__ x, const float* __restrict__ g,
                 const float* __restrict__ b, float* __restrict__ outf,
                 bf16* __restrict__ ohi, bf16* __restrict__ olo)
{
    const int row = blockIdx.x;
    const float* xr = x + (size_t)row * EMB;
    const int t = threadIdx.x;

    const float4 v = *(const float4*)(xr + t * 4);
    float s  = v.x + v.y + v.z + v.w;
    float ss = v.x * v.x + v.y * v.y + v.z * v.z + v.w * v.w;

    __shared__ float shs[8], shss[8], shmu[1], shinv[1];
    const int lane = t & 31, w = t >> 5;
    #pragma unroll
    for (int o = 16; o > 0; o >>= 1) {
        s  += __shfl_down_sync(0xffffffffu, s,  o);
        ss += __shfl_down_sync(0xffffffffu, ss, o);
    }
    if (lane == 0) { shs[w] = s; shss[w] = ss; }
    __syncthreads();
    if (w == 0) {
        float s2  = (lane < 8) ? shs[lane]  : 0.f;
        float ss2 = (lane < 8) ? shss[lane] : 0.f;
        #pragma unroll
        for (int o = 4; o > 0; o >>= 1) {
            s2  += __shfl_down_sync(0xffffffffu, s2,  o);
            ss2 += __shfl_down_sync(0xffffffffu, ss2, o);
        }
        if (lane == 0) {
            const float mu  = s2 * (1.f / EMB);
            const float var = ss2 * (1.f / EMB) - mu * mu;
            shmu[0]  = mu;
            shinv[0] = rsqrtf(var + 1e-5f);
        }
    }
    __syncthreads();
    const float mu = shmu[0], inv = shinv[0];

    const float4 gv = *(const float4*)(g + t * 4);
    const float4 bv = *(const float4*)(b + t * 4);
    float4 o;
    o.x = (v.x - mu) * inv * gv.x + bv.x;
    o.y = (v.y - mu) * inv * gv.y + bv.y;
    o.z = (v.z - mu) * inv * gv.z + bv.z;
    o.w = (v.w - mu) * inv * gv.w + bv.w;
    const size_t off = (size_t)row * EMB + t * 4;
    if (BF == 0) {
        *(float4*)(outf + off) = o;
    } else {
        uint2 H, L;
        split4(o, H, L);
        *(uint2*)(ohi + off) = H;
        *(uint2*)(olo + off) = L;
    }
}

// ---------------- launch ----------------
extern "C" void kernel_launch(void* const* d_in, const int* in_sizes, int n_in,
                              void* d_out, int out_size)
{
    const float* value  = (const float*)d_in[0];
    const float* key_t  = (const float*)d_in[1];
    const float* query  = (const float*)d_in[2];
    const float* embed0 = (const float*)d_in[3];
    const float* Wq = (const float*)d_in[4];
    const float* bq = (const float*)d_in[5];
    const float* Wk = (const float*)d_in[6];
    const float* bk = (const float*)d_in[7];
    const float* Wv = (const float*)d_in[8];
    const float* bv = (const float*)d_in[9];
    const float* W1 = (const float*)d_in[10];
    const float* b1 = (const float*)d_in[11];
    const float* W2 = (const float*)d_in[12];
    const float* b2 = (const float*)d_in[13];
    const float* g1  = (const float*)d_in[14];
    const float* be1 = (const float*)d_in[15];
    const float* g2  = (const float*)d_in[16];
    const float* be2 = (const float*)d_in[17];

    // symbol addresses
    bf16 *p_qinh, *p_qinl, *p_kinh, *p_kinl, *p_vinh, *p_vinl;
    bf16 *p_wqh, *p_wql, *p_wkh, *p_wkl, *p_wvh, *p_wvl, *p_w1h, *p_w1l, *p_w2h, *p_w2l;
    bf16 *p_qh, *p_ql, *p_kh, *p_kl, *p_vth, *p_vtl, *p_ath, *p_atl, *p_xh, *p_xl, *p_hh, *p_hl;
    float *p_attnf, *p_x, *p_y;
    cudaGetSymbolAddress((void**)&p_qinh, qin_hi); cudaGetSymbolAddress((void**)&p_qinl, qin_lo);
    cudaGetSymbolAddress((void**)&p_kinh, kin_hi); cudaGetSymbolAddress((void**)&p_kinl, kin_lo);
    cudaGetSymbolAddress((void**)&p_vinh, vin_hi); cudaGetSymbolAddress((void**)&p_vinl, vin_lo);
    cudaGetSymbolAddress((void**)&p_wqh, wq_hi);   cudaGetSymbolAddress((void**)&p_wql, wq_lo);
    cudaGetSymbolAddress((void**)&p_wkh, wk_hi);   cudaGetSymbolAddress((void**)&p_wkl, wk_lo);
    cudaGetSymbolAddress((void**)&p_wvh, wv_hi);   cudaGetSymbolAddress((void**)&p_wvl, wv_lo);
    cudaGetSymbolAddress((void**)&p_w1h, w1_hi);   cudaGetSymbolAddress((void**)&p_w1l, w1_lo);
    cudaGetSymbolAddress((void**)&p_w2h, w2_hi);   cudaGetSymbolAddress((void**)&p_w2l, w2_lo);
    cudaGetSymbolAddress((void**)&p_qh, q_hi);     cudaGetSymbolAddress((void**)&p_ql, q_lo);
    cudaGetSymbolAddress((void**)&p_kh, k_hi);     cudaGetSymbolAddress((void**)&p_kl, k_lo);
    cudaGetSymbolAddress((void**)&p_vth, vt_hi);   cudaGetSymbolAddress((void**)&p_vtl, vt_lo);
    cudaGetSymbolAddress((void**)&p_ath, at_hi);   cudaGetSymbolAddress((void**)&p_atl, at_lo);
    cudaGetSymbolAddress((void**)&p_xh, x_hi);     cudaGetSymbolAddress((void**)&p_xl, x_lo);
    cudaGetSymbolAddress((void**)&p_hh, h_hi);     cudaGetSymbolAddress((void**)&p_hl, h_lo);
    cudaGetSymbolAddress((void**)&p_attnf, g_attnf);
    cudaGetSymbolAddress((void**)&p_x, g_x);
    cudaGetSymbolAddress((void**)&p_y, g_y);

    #define SET_SMEM(KER) cudaFuncSetAttribute(KER, cudaFuncAttributeMaxDynamicSharedMemorySize, SMEM_TOTAL)
    SET_SMEM((hmma_gemm<0,false,true,false>));
    SET_SMEM((hmma_gemm<0,false,true,true>));
    SET_SMEM((hmma_gemm<2,true,true,false>));
    SET_SMEM((hmma_gemm<0,true,false,false>));
    SET_SMEM((hmma_gemm<1,false,true,false>));

    float* outp = (float*)d_out;
    const long long outElems  = (long long)MROWS * EMB;
    const long long attnElems = (long long)NBATCH * SEQ * SEQ;
    float* attnf = ((long long)out_size >= outElems + attnElems) ? (outp + outElems) : p_attnf;

    dim3 blk(256);
    const float scale = 1.0f / 32.0f;
    const size_t sQK = (size_t)SEQ * EMB;
    const size_t sAT = (size_t)SEQ * SEQ;
    const size_t sVT = (size_t)EMB * SEQ;

    // 0) input/weight splits
    cvt_split<<<MROWS*EMB/1024, blk>>>(query, embed0, p_qinh, p_qinl);
    cvt_split<<<MROWS*EMB/1024, blk>>>(key_t, embed0, p_kinh, p_kinl);
    cvt_split<<<MROWS*EMB/1024, blk>>>(value, embed0, p_vinh, p_vinl);
    cvt_split<<<EMB*EMB/1024,   blk>>>(Wq, nullptr, p_wqh, p_wql);
    cvt_split<<<EMB*EMB/1024,   blk>>>(Wk, nullptr, p_wkh, p_wkl);
    cvt_split<<<EMB*EMB/1024,   blk>>>(Wv, nullptr, p_wvh, p_wvl);
    cvt_split<<<FFDIM*EMB/1024, blk>>>(W1, nullptr, p_w1h, p_w1l);
    cvt_split<<<EMB*FFDIM/1024, blk>>>(W2, nullptr, p_w2h, p_w2l);

    // 1) QKV projections -> bf16 planes (V transposed)
    dim3 gQKV(EMB / 128, MROWS / 128, 1);
    hmma_gemm<0,false,true,false><<<gQKV, blk, SMEM_TOTAL>>>(
        p_qinh, p_qinl, p_wqh, p_wql, bq, nullptr, p_qh, p_ql, EMB, EMB, 0, 0, 0, 0.f);
    hmma_gemm<0,false,true,false><<<gQKV, blk, SMEM_TOTAL>>>(
        p_kinh, p_kinl, p_wkh, p_wkl, bk, nullptr, p_kh, p_kl, EMB, EMB, 0, 0, 0, 0.f);
    hmma_gemm<0,false,true,true><<<gQKV, blk, SMEM_TOTAL>>>(
        p_vinh, p_vinl, p_wvh, p_wvl, bv, nullptr, p_vth, p_vtl, EMB, SEQ, 0, 0, 0, 0.f);

    // 2) attn = sigmoid(q @ k^T * scale): fp32 to output + bf16 planes
    dim3 gS(SEQ / 128, SEQ / 128, NBATCH);
    hmma_gemm<2,true,true,false><<<gS, blk, SMEM_TOTAL>>>(
        p_qh, p_ql, p_kh, p_kl, nullptr, attnf, p_ath, p_atl, EMB, SEQ, sQK, sQK, sAT, scale);

    // 3) x = attn @ v  (B = V^T planes)
    dim3 gAV(EMB / 128, SEQ / 128, NBATCH);
    hmma_gemm<0,true,false,false><<<gAV, blk, SMEM_TOTAL>>>(
        p_ath, p_atl, p_vth, p_vtl, nullptr, p_x, nullptr, nullptr, SEQ, EMB, sAT, sVT, sQK, 0.f);

    // 4) LN1 -> bf16 planes
    layernorm_kernel<1><<<MROWS, 256>>>(p_x, g1, be1, nullptr, p_xh, p_xl);

    // 5) FFN1 = relu(x @ W1^T + b1) -> bf16 planes
    dim3 gF1(FFDIM / 128, MROWS / 128, 1);
    hmma_gemm<1,false,true,false><<<gF1, blk, SMEM_TOTAL>>>(
        p_xh, p_xl, p_w1h, p_w1l, b1, nullptr, p_hh, p_hl, EMB, FFDIM, 0, 0, 0, 0.f);

    // 6) FFN2 = h @ W2^T + b2 -> fp32
    dim3 gF2(EMB / 128, MROWS / 128, 1);
    hmma_gemm<0,true,false,false><<<gF2, blk, SMEM_TOTAL>>>(
        p_hh, p_hl, p_w2h, p_w2l, b2, p_y, nullptr, nullptr, FFDIM, EMB, 0, 0, 0, 0.f);

    // 7) LN2 -> out
    layernorm_kernel<0><<<MROWS, 256>>>(p_y, g2, be2, outp, nullptr, nullptr);
}

// round 7
// speedup vs baseline: 1.3355x; 1.2194x over previous
#include <cuda_runtime.h>
#include <cuda_fp16.h>
#include <cstdint>
#include <math.h>

#define NBATCH 2
#define SEQ    4096
#define EMB    1024
#define FFDIM  4096
#define MROWS  (NBATCH*SEQ)   // 8192

typedef __half h16;

// ---------------- scratch (device globals; allocation-free) ----------------
__device__ h16 qin_hi[MROWS*EMB], qin_lo[MROWS*EMB];
__device__ h16 kin_hi[MROWS*EMB], kin_lo[MROWS*EMB];
__device__ h16 vin_hi[MROWS*EMB], vin_lo[MROWS*EMB];
__device__ h16 wq_hi[EMB*EMB];
__device__ h16 wk_hi[EMB*EMB];
__device__ h16 wv_hi[EMB*EMB];
__device__ h16 w1_hi[FFDIM*EMB];
__device__ h16 w2_hi[EMB*FFDIM];
__device__ h16 q_hi[MROWS*EMB],  q_lo[MROWS*EMB];
__device__ h16 k_hi[MROWS*EMB];
__device__ h16 vt_hi[NBATCH*EMB*SEQ];
__device__ h16 at_hi[(size_t)NBATCH*SEQ*SEQ], at_lo[(size_t)NBATCH*SEQ*SEQ];
__device__ h16 x_hi[MROWS*EMB],  x_lo[MROWS*EMB];
__device__ h16 h_hi[MROWS*FFDIM], h_lo[MROWS*FFDIM];
__device__ float g_attnf[(size_t)NBATCH*SEQ*SEQ];
__device__ float g_x[MROWS*EMB];
__device__ float g_y[MROWS*EMB];

// ---------------- helpers ----------------
__device__ __forceinline__ uint32_t smem_u32(const void* p) {
    uint32_t a;
    asm("{ .reg .u64 t; cvta.to.shared.u64 t, %1; cvt.u32.u64 %0, t; }" : "=r"(a) : "l"(p));
    return a;
}
__device__ __forceinline__ void ldsm4(uint32_t r[4], uint32_t addr) {
    asm volatile("ldmatrix.sync.aligned.m8n8.x4.shared.b16 {%0,%1,%2,%3}, [%4];"
                 : "=r"(r[0]), "=r"(r[1]), "=r"(r[2]), "=r"(r[3]) : "r"(addr));
}
__device__ __forceinline__ void mma16816(float c[4], const uint32_t a[4],
                                         uint32_t b0, uint32_t b1) {
    asm volatile("mma.sync.aligned.m16n8k16.row.col.f32.f16.f16.f32 "
                 "{%0,%1,%2,%3}, {%4,%5,%6,%7}, {%8,%9}, {%0,%1,%2,%3};"
                 : "+f"(c[0]), "+f"(c[1]), "+f"(c[2]), "+f"(c[3])
                 : "r"(a[0]), "r"(a[1]), "r"(a[2]), "r"(a[3]), "r"(b0), "r"(b1));
}
__device__ __forceinline__ void cpasync16(uint32_t dst, const void* src) {
    asm volatile("cp.async.cg.shared.global [%0], [%1], 16;" :: "r"(dst), "l"(src) : "memory");
}
#define CP_COMMIT() asm volatile("cp.async.commit_group;" ::: "memory")
#define CP_WAIT(n)  asm volatile("cp.async.wait_group %0;" :: "n"(n) : "memory")

// fp32x4 -> hi/lo fp16x4 (as uint2 each)
__device__ __forceinline__ void split4(const float4& f, uint2& H, uint2& L) {
    __half2 h0 = __floats2half2_rn(f.x, f.y);
    __half2 h1 = __floats2half2_rn(f.z, f.w);
    __half2 l0 = __floats2half2_rn(f.x - __half2float(h0.x), f.y - __half2float(h0.y));
    __half2 l1 = __floats2half2_rn(f.z - __half2float(h1.x), f.w - __half2float(h1.y));
    H.x = *reinterpret_cast<uint32_t*>(&h0);
    H.y = *reinterpret_cast<uint32_t*>(&h1);
    L.x = *reinterpret_cast<uint32_t*>(&l0);
    L.y = *reinterpret_cast<uint32_t*>(&l1);
}

// ---------------- elementwise converter: hi (+optional lo) split of (a [+ b]) ----
__global__ void __launch_bounds__(256)
cvt_split(const float* __restrict__ a, const float* __restrict__ b,
          h16* __restrict__ hi, h16* __restrict__ lo)
{
    const size_t i4 = ((size_t)blockIdx.x * 256 + threadIdx.x) * 4;
    float4 f = *(const float4*)(a + i4);
    if (b) {
        const float4 e = *(const float4*)(b + i4);
        f.x += e.x; f.y += e.y; f.z += e.z; f.w += e.w;
    }
    uint2 H, L;
    split4(f, H, L);
    *(uint2*)(hi + i4) = H;
    if (lo) *(uint2*)(lo + i4) = L;
}

// ---------------- HMMA GEMM: C[M,N] = op( A[M,K] @ B[N,K]^T ) -----------------
// A pre-split fp16 hi/lo planes; B fp16 hi plane only (2-product scheme).
// K-chunk 64. 3-stage cp.async pipeline. Stage 48KB: Ahi(16K) | Alo(16K) | Bhi(16K),
// each plane 128 rows x 128B, SW128 swizzle.
// OP: 0 = +bias, 1 = relu(+bias), 2 = sigmoid(acc*scale)
#define NS 3
#define PLANE_BYTES 16384
#define STAGE_BYTES 49152
#define EPI_PITCH   132
#define SMEM_TOTAL  (NS*STAGE_BYTES + 1024)

template<int OP, bool OUTF, bool OUTB, bool TRANS>
__global__ void __launch_bounds__(256)
hmma_gemm(const h16* __restrict__ Ahi, const h16* __restrict__ Alo,
          const h16* __restrict__ Bhi, const float* __restrict__ bias,
          float* __restrict__ Cf, h16* __restrict__ Chi, h16* __restrict__ Clo,
          int K, int ldC, size_t sA, size_t sB, size_t sC, float scale)
{
    extern __shared__ char smem[];
    const uint32_t sbase = (smem_u32(smem) + 1023) & ~1023u;

    const int t = threadIdx.x;
    const int w = t >> 5, lane = t & 31;
    const int wm = w >> 2, wn = w & 3;            // warp grid 2 x 4

    const int bz = blockIdx.z;
    Ahi += (size_t)bz * sA;  Alo += (size_t)bz * sA;
    Bhi += (size_t)bz * sB;
    const int mBase = blockIdx.y * 128;
    const int nBase = blockIdx.x * 128;

    float acc[4][4][4];
    #pragma unroll
    for (int mi = 0; mi < 4; mi++)
        #pragma unroll
        for (int nj = 0; nj < 4; nj++)
            #pragma unroll
            for (int e = 0; e < 4; e++)
                acc[mi][nj][e] = 0.f;

    const int nk = K >> 6;

    // cp.async mapping: row = t>>1, 4 x 16B chunks per plane per thread
    const int srow = t >> 1;
    const uint32_t srx = ((uint32_t)(srow & 7)) << 4;
    const uint32_t srowoff = (uint32_t)srow * 128;
    const size_t gArow = (size_t)(mBase + srow) * K;
    const size_t gBrow = (size_t)(nBase + srow) * K;

    auto ISSUE = [&](int kc, int s) {
        const int kb = kc << 6;
        const uint32_t st = sbase + (uint32_t)s * STAGE_BYTES;
        #pragma unroll
        for (int c = 0; c < 4; c++) {
            const int col16 = (t & 1) * 4 + c;
            const uint32_t d = srowoff + (((uint32_t)col16 * 16) ^ srx);
            const int kk = kb + col16 * 8;
            cpasync16(st + d,                   Ahi + gArow + kk);
            cpasync16(st + PLANE_BYTES + d,     Alo + gArow + kk);
            cpasync16(st + 2*PLANE_BYTES + d,   Bhi + gBrow + kk);
        }
    };

    // ldmatrix addressing
    const uint32_t arow128 = (uint32_t)(wm * 64 + (lane & 15)) * 128;
    const uint32_t a16     = ((uint32_t)(lane >> 4)) << 4;
    const uint32_t axor    = ((uint32_t)(lane & 7)) << 4;
    const uint32_t brow128 = (uint32_t)(wn * 32 + ((lane >> 4) << 3) + (lane & 7)) * 128;
    const uint32_t b16     = ((uint32_t)((lane >> 3) & 1)) << 4;

    auto COMPUTE = [&](int s) {
        const uint32_t stAh = sbase + (uint32_t)s * STAGE_BYTES;
        const uint32_t stAl = stAh + PLANE_BYTES;
        const uint32_t stB  = stAh + 2*PLANE_BYTES;
        #pragma unroll
        for (int ki = 0; ki < 4; ki++) {
            const uint32_t kba = (uint32_t)(ki * 32);
            uint32_t Ah[4][4], Al[4][4], Bn[4][2];
            #pragma unroll
            for (int mi = 0; mi < 4; mi++) {
                ldsm4(Ah[mi], stAh + arow128 + mi * 2048 + ((kba + a16) ^ axor));
                ldsm4(Al[mi], stAl + arow128 + mi * 2048 + ((kba + a16) ^ axor));
            }
            #pragma unroll
            for (int nx = 0; nx < 2; nx++) {
                uint32_t tb[4];
                ldsm4(tb, stB + brow128 + nx * 2048 + ((kba + b16) ^ axor));
                Bn[nx*2][0]   = tb[0]; Bn[nx*2][1]   = tb[1];
                Bn[nx*2+1][0] = tb[2]; Bn[nx*2+1][1] = tb[3];
            }
            // product 1: Ah * Bh  (reuse distance 16)
            #pragma unroll
            for (int nj = 0; nj < 4; nj++)
                #pragma unroll
                for (int mi = 0; mi < 4; mi++)
                    mma16816(acc[mi][nj], Ah[mi], Bn[nj][0], Bn[nj][1]);
            // product 2: Al * Bh
            #pragma unroll
            for (int nj = 0; nj < 4; nj++)
                #pragma unroll
                for (int mi = 0; mi < 4; mi++)
                    mma16816(acc[mi][nj], Al[mi], Bn[nj][0], Bn[nj][1]);
        }
    };

    // prologue
    #pragma unroll
    for (int s = 0; s < NS - 1; s++) { ISSUE(s, s); CP_COMMIT(); }

    for (int kc = 0; kc < nk; kc++) {
        CP_WAIT(NS - 2);
        __syncthreads();
        const int kn = kc + NS - 1;
        if (kn < nk) { ISSUE(kn, kn % NS); CP_COMMIT(); }
        COMPUTE(kc % NS);
    }
    __syncthreads();

    // ---- epilogue: regs -> SMEM (pitch 132) -> vectorized stores
    float* epi = (float*)smem;
    const int g  = lane >> 2;
    const int tq = lane & 3;
    #pragma unroll
    for (int mi = 0; mi < 4; mi++) {
        #pragma unroll
        for (int nj = 0; nj < 4; nj++) {
            const int col = wn * 32 + nj * 8 + tq * 2;
            #pragma unroll
            for (int half = 0; half < 2; half++) {
                const int m = wm * 64 + mi * 16 + g + half * 8;
                float v0 = acc[mi][nj][half*2 + 0];
                float v1 = acc[mi][nj][half*2 + 1];
                if (OP == 2) {
                    v0 = 1.f / (1.f + __expf(-v0 * scale));
                    v1 = 1.f / (1.f + __expf(-v1 * scale));
                } else {
                    if (bias) { v0 += bias[nBase + col]; v1 += bias[nBase + col + 1]; }
                    if (OP == 1) { v0 = fmaxf(v0, 0.f); v1 = fmaxf(v1, 0.f); }
                }
                if (TRANS) {
                    epi[(col)     * EPI_PITCH + m] = v0;
                    epi[(col + 1) * EPI_PITCH + m] = v1;
                } else {
                    epi[m * EPI_PITCH + col]     = v0;
                    epi[m * EPI_PITCH + col + 1] = v1;
                }
            }
        }
    }
    __syncthreads();

    const int r  = t >> 1;
    const int ch = (t & 1) * 64;
    size_t rowOff;
    if (TRANS) {
        const size_t boffs = (size_t)(mBase >> 12) * ((size_t)EMB * SEQ);
        rowOff = boffs + (size_t)(nBase + r) * SEQ + (size_t)(mBase & (SEQ - 1)) + ch;
    } else {
        rowOff = (size_t)bz * sC + (size_t)(mBase + r) * ldC + nBase + ch;
    }
    #pragma unroll
    for (int i = 0; i < 16; i++) {
        const float* e = &epi[r * EPI_PITCH + ch + i * 4];
        const float4 f = make_float4(e[0], e[1], e[2], e[3]);
        if (OUTF) *(float4*)(Cf + rowOff + i * 4) = f;
        if (OUTB) {
            uint2 H, L;
            split4(f, H, L);
            *(uint2*)(Chi + rowOff + i * 4) = H;
            if (Clo) *(uint2*)(Clo + rowOff + i * 4) = L;
        }
    }
}

// ---------------- LayerNorm ----------------
// BF=0: write fp32; BF=1: write fp16 hi/lo split
template<int BF>
__global__ void __launch_bounds__(256)
layernorm_kernel(const float* __restrict__ x, const float* __restrict__ g,
                 const float* __restrict__ b, float* __restrict__ outf,
                 h16* __restrict__ ohi, h16* __restrict__ olo)
{
    const int row = blockIdx.x;
    const float* xr = x + (size_t)row * EMB;
    const int t = threadIdx.x;

    const float4 v = *(const float4*)(xr + t * 4);
    float s  = v.x + v.y + v.z + v.w;
    float ss = v.x * v.x + v.y * v.y + v.z * v.z + v.w * v.w;

    __shared__ float shs[8], shss[8], shmu[1], shinv[1];
    const int lane = t & 31, w = t >> 5;
    #pragma unroll
    for (int o = 16; o > 0; o >>= 1) {
        s  += __shfl_down_sync(0xffffffffu, s,  o);
        ss += __shfl_down_sync(0xffffffffu, ss, o);
    }
    if (lane == 0) { shs[w] = s; shss[w] = ss; }
    __syncthreads();
    if (w == 0) {
        float s2  = (lane < 8) ? shs[lane]  : 0.f;
        float ss2 = (lane < 8) ? shss[lane] : 0.f;
        #pragma unroll
        for (int o = 4; o > 0; o >>= 1) {
            s2  += __shfl_down_sync(0xffffffffu, s2,  o);
            ss2 += __shfl_down_sync(0xffffffffu, ss2, o);
        }
        if (lane == 0) {
            const float mu  = s2 * (1.f / EMB);
            const float var = ss2 * (1.f / EMB) - mu * mu;
            shmu[0]  = mu;
            shinv[0] = rsqrtf(var + 1e-5f);
        }
    }
    __syncthreads();
    const float mu = shmu[0], inv = shinv[0];

    const float4 gv = *(const float4*)(g + t * 4);
    const float4 bv = *(const float4*)(b + t * 4);
    float4 o;
    o.x = (v.x - mu) * inv * gv.x + bv.x;
    o.y = (v.y - mu) * inv * gv.y + bv.y;
    o.z = (v.z - mu) * inv * gv.z + bv.z;
    o.w = (v.w - mu) * inv * gv.w + bv.w;
    const size_t off = (size_t)row * EMB + t * 4;
    if (BF == 0) {
        *(float4*)(outf + off) = o;
    } else {
        uint2 H, L;
        split4(o, H, L);
        *(uint2*)(ohi + off) = H;
        *(uint2*)(olo + off) = L;
    }
}

// ---------------- launch ----------------
extern "C" void kernel_launch(void* const* d_in, const int* in_sizes, int n_in,
                              void* d_out, int out_size)
{
    const float* value  = (const float*)d_in[0];
    const float* key_t  = (const float*)d_in[1];
    const float* query  = (const float*)d_in[2];
    const float* embed0 = (const float*)d_in[3];
    const float* Wq = (const float*)d_in[4];
    const float* bq = (const float*)d_in[5];
    const float* Wk = (const float*)d_in[6];
    const float* bk = (const float*)d_in[7];
    const float* Wv = (const float*)d_in[8];
    const float* bv = (const float*)d_in[9];
    const float* W1 = (const float*)d_in[10];
    const float* b1 = (const float*)d_in[11];
    const float* W2 = (const float*)d_in[12];
    const float* b2 = (const float*)d_in[13];
    const float* g1  = (const float*)d_in[14];
    const float* be1 = (const float*)d_in[15];
    const float* g2  = (const float*)d_in[16];
    const float* be2 = (const float*)d_in[17];

    h16 *p_qinh, *p_qinl, *p_kinh, *p_kinl, *p_vinh, *p_vinl;
    h16 *p_wqh, *p_wkh, *p_wvh, *p_w1h, *p_w2h;
    h16 *p_qh, *p_ql, *p_kh, *p_vth, *p_ath, *p_atl, *p_xh, *p_xl, *p_hh, *p_hl;
    float *p_attnf, *p_x, *p_y;
    cudaGetSymbolAddress((void**)&p_qinh, qin_hi); cudaGetSymbolAddress((void**)&p_qinl, qin_lo);
    cudaGetSymbolAddress((void**)&p_kinh, kin_hi); cudaGetSymbolAddress((void**)&p_kinl, kin_lo);
    cudaGetSymbolAddress((void**)&p_vinh, vin_hi); cudaGetSymbolAddress((void**)&p_vinl, vin_lo);
    cudaGetSymbolAddress((void**)&p_wqh, wq_hi);
    cudaGetSymbolAddress((void**)&p_wkh, wk_hi);
    cudaGetSymbolAddress((void**)&p_wvh, wv_hi);
    cudaGetSymbolAddress((void**)&p_w1h, w1_hi);
    cudaGetSymbolAddress((void**)&p_w2h, w2_hi);
    cudaGetSymbolAddress((void**)&p_qh, q_hi);     cudaGetSymbolAddress((void**)&p_ql, q_lo);
    cudaGetSymbolAddress((void**)&p_kh, k_hi);
    cudaGetSymbolAddress((void**)&p_vth, vt_hi);
    cudaGetSymbolAddress((void**)&p_ath, at_hi);   cudaGetSymbolAddress((void**)&p_atl, at_lo);
    cudaGetSymbolAddress((void**)&p_xh, x_hi);     cudaGetSymbolAddress((void**)&p_xl, x_lo);
    cudaGetSymbolAddress((void**)&p_hh, h_hi);     cudaGetSymbolAddress((void**)&p_hl, h_lo);
    cudaGetSymbolAddress((void**)&p_attnf, g_attnf);
    cudaGetSymbolAddress((void**)&p_x, g_x);
    cudaGetSymbolAddress((void**)&p_y, g_y);

    #define SET_SMEM(KER) cudaFuncSetAttribute(KER, cudaFuncAttributeMaxDynamicSharedMemorySize, SMEM_TOTAL)
    SET_SMEM((hmma_gemm<0,false,true,false>));
    SET_SMEM((hmma_gemm<0,false,true,true>));
    SET_SMEM((hmma_gemm<2,true,true,false>));
    SET_SMEM((hmma_gemm<0,true,false,false>));
    SET_SMEM((hmma_gemm<1,false,true,false>));

    float* outp = (float*)d_out;
    const long long outElems  = (long long)MROWS * EMB;
    const long long attnElems = (long long)NBATCH * SEQ * SEQ;
    float* attnf = ((long long)out_size >= outElems + attnElems) ? (outp + outElems) : p_attnf;

    dim3 blk(256);
    const float scale = 1.0f / 32.0f;
    const size_t sQK = (size_t)SEQ * EMB;
    const size_t sAT = (size_t)SEQ * SEQ;
    const size_t sVT = (size_t)EMB * SEQ;

    // 0) input/weight conversions
    cvt_split<<<MROWS*EMB/1024, blk>>>(query, embed0, p_qinh, p_qinl);
    cvt_split<<<MROWS*EMB/1024, blk>>>(key_t, embed0, p_kinh, p_kinl);
    cvt_split<<<MROWS*EMB/1024, blk>>>(value, embed0, p_vinh, p_vinl);
    cvt_split<<<EMB*EMB/1024,   blk>>>(Wq, nullptr, p_wqh, nullptr);
    cvt_split<<<EMB*EMB/1024,   blk>>>(Wk, nullptr, p_wkh, nullptr);
    cvt_split<<<EMB*EMB/1024,   blk>>>(Wv, nullptr, p_wvh, nullptr);
    cvt_split<<<FFDIM*EMB/1024, blk>>>(W1, nullptr, p_w1h, nullptr);
    cvt_split<<<EMB*FFDIM/1024, blk>>>(W2, nullptr, p_w2h, nullptr);

    // 1) QKV projections (q -> hi+lo; k -> hi; v -> transposed hi)
    dim3 gQKV(EMB / 128, MROWS / 128, 1);
    hmma_gemm<0,false,true,false><<<gQKV, blk, SMEM_TOTAL>>>(
        p_qinh, p_qinl, p_wqh, bq, nullptr, p_qh, p_ql, EMB, EMB, 0, 0, 0, 0.f);
    hmma_gemm<0,false,true,false><<<gQKV, blk, SMEM_TOTAL>>>(
        p_kinh, p_kinl, p_wkh, bk, nullptr, p_kh, nullptr, EMB, EMB, 0, 0, 0, 0.f);
    hmma_gemm<0,false,true,true><<<gQKV, blk, SMEM_TOTAL>>>(
        p_vinh, p_vinl, p_wvh, bv, nullptr, p_vth, nullptr, EMB, SEQ, 0, 0, 0, 0.f);

    // 2) attn = sigmoid(q @ k^T * scale): fp32 output + fp16 hi/lo planes
    dim3 gS(SEQ / 128, SEQ / 128, NBATCH);
    hmma_gemm<2,true,true,false><<<gS, blk, SMEM_TOTAL>>>(
        p_qh, p_ql, p_kh, nullptr, attnf, p_ath, p_atl, EMB, SEQ, sQK, sQK, sAT, scale);

    // 3) x = attn @ v (B = V^T hi plane)
    dim3 gAV(EMB / 128, SEQ / 128, NBATCH);
    hmma_gemm<0,true,false,false><<<gAV, blk, SMEM_TOTAL>>>(
        p_ath, p_atl, p_vth, nullptr, p_x, nullptr, nullptr, SEQ, EMB, sAT, sVT, sQK, 0.f);

    // 4) LN1 -> fp16 hi/lo planes
    layernorm_kernel<1><<<MROWS, 256>>>(p_x, g1, be1, nullptr, p_xh, p_xl);

    // 5) FFN1 = relu(x @ W1^T + b1) -> fp16 hi/lo planes
    dim3 gF1(FFDIM / 128, MROWS / 128, 1);
    hmma_gemm<1,false,true,false><<<gF1, blk, SMEM_TOTAL>>>(
        p_xh, p_xl, p_w1h, b1, nullptr, p_hh, p_hl, EMB, FFDIM, 0, 0, 0, 0.f);

    // 6) FFN2 = h @ W2^T + b2 -> fp32
    dim3 gF2(EMB / 128, MROWS / 128, 1);
    hmma_gemm<0,true,false,false><<<gF2, blk, SMEM_TOTAL>>>(
        p_hh, p_hl, p_w2h, b2, p_y, nullptr, nullptr, FFDIM, EMB, 0, 0, 0, 0.f);

    // 7) LN2 -> out
    layernorm_kernel<0><<<MROWS, 256>>>(p_y, g2, be2, outp, nullptr, nullptr);
}